// round 1
// baseline (speedup 1.0000x reference)
#include <cuda_runtime.h>
#include <math.h>

// Problem dims (fixed by the dataset)
#define BB   16
#define TT   1024
#define DD   256        // key_dim == e_dim
#define NE   512        // codebook size
#define MR   (BB*TT)    // 16384 rows

// ---------------- scratch (__device__ globals: allocation-free) ----------------
__device__ float g_ksn[MR * DD];        // normalized key_soft         (16 MB)
__device__ float g_w[MR * NE];          // softmax weights             (32 MB)
__device__ float g_keys_norm[NE * DD];  // normalized keys
__device__ float g_vp_norm[NE * DD];    // normalized vparams
__device__ float g_vp_normT[DD * NE];   // vp_norm transposed [E, n_e]

// ---------------- rowwise L2 normalize, 256 cols, one block per row ------------
__global__ void rownorm256(const float* __restrict__ in, float* __restrict__ out) {
    int r = blockIdx.x;
    int t = threadIdx.x;                  // 256 threads
    float v = in[(long)r * 256 + t];
    float s = v * v;
    #pragma unroll
    for (int o = 16; o; o >>= 1) s += __shfl_xor_sync(0xffffffffu, s, o);
    __shared__ float ws[8];
    if ((t & 31) == 0) ws[t >> 5] = s;
    __syncthreads();
    if (t < 8) {
        float x = ws[t];
        #pragma unroll
        for (int o = 4; o; o >>= 1) x += __shfl_xor_sync(0xffu, x, o);
        if (t == 0) ws[0] = x;
    }
    __syncthreads();
    float scale = 1.0f / fmaxf(sqrtf(ws[0]), 1e-12f);
    out[(long)r * 256 + t] = v * scale;
}

// ---------------- transpose vp_norm [512,256] -> vp_normT [256,512] ------------
__global__ void transpose_vp() {
    __shared__ float tile[32][33];
    int x = blockIdx.x * 32 + threadIdx.x;   // src col (0..255)
    int y = blockIdx.y * 32 + threadIdx.y;   // src row (0..511)
    tile[threadIdx.y][threadIdx.x] = g_vp_norm[y * 256 + x];
    __syncthreads();
    int tx = blockIdx.y * 32 + threadIdx.x;  // dst col = src row
    int ty = blockIdx.x * 32 + threadIdx.y;  // dst row = src col
    g_vp_normT[ty * 512 + tx] = tile[threadIdx.x][threadIdx.y];
}

// ---------------- softmax + argmax + hard gather, one block per row ------------
// reads score_ksh row (512), writes g_w row, idx (as float), and vparams_hard row
__global__ void softmax_argmax(const float* __restrict__ ksh,
                               float* __restrict__ out_idx,
                               float* __restrict__ out_hard) {
    int r = blockIdx.x;
    int t = threadIdx.x;                  // 256 threads, 2 cols each
    const float* row = ksh + (long)r * NE;
    float s0 = row[t], s1 = row[t + 256];
    float bv; int bi;
    if (s1 > s0) { bv = s1; bi = t + 256; } else { bv = s0; bi = t; } // tie -> lower idx
    #pragma unroll
    for (int o = 16; o; o >>= 1) {
        float ov = __shfl_xor_sync(0xffffffffu, bv, o);
        int   oi = __shfl_xor_sync(0xffffffffu, bi, o);
        if (ov > bv || (ov == bv && oi < bi)) { bv = ov; bi = oi; }
    }
    __shared__ float sv[8]; __shared__ int si[8];
    if ((t & 31) == 0) { sv[t >> 5] = bv; si[t >> 5] = bi; }
    __syncthreads();
    if (t < 8) {
        float x = sv[t]; int xi = si[t];
        #pragma unroll
        for (int o = 4; o; o >>= 1) {
            float ov = __shfl_xor_sync(0xffu, x, o);
            int   oi = __shfl_xor_sync(0xffu, xi, o);
            if (ov > x || (ov == x && oi < xi)) { x = ov; xi = oi; }
        }
        if (t == 0) { sv[0] = x; si[0] = xi; }
    }
    __syncthreads();
    float m = sv[0]; int idx = si[0];
    float e0 = expf(s0 - m), e1 = expf(s1 - m);
    float s = e0 + e1;
    #pragma unroll
    for (int o = 16; o; o >>= 1) s += __shfl_xor_sync(0xffffffffu, s, o);
    __shared__ float ss[8];
    if ((t & 31) == 0) ss[t >> 5] = s;
    __syncthreads();
    if (t < 8) {
        float x = ss[t];
        #pragma unroll
        for (int o = 4; o; o >>= 1) x += __shfl_xor_sync(0xffu, x, o);
        if (t == 0) ss[0] = x;
    }
    __syncthreads();
    float inv = 1.0f / ss[0];
    g_w[(long)r * NE + t]       = e0 * inv;
    g_w[(long)r * NE + t + 256] = e1 * inv;
    if (t == 0) out_idx[r] = (float)idx;
    // vparams_hard = l2norm(vparams[idx]) == vp_norm[idx]
    out_hard[(long)r * 256 + t] = g_vp_norm[(long)idx * 256 + t];
}

// ---------------- generic NT SGEMM: C[M,N] = A[M,K] * B[N,K]^T -----------------
// row-major A (stride K), row-major B (stride K), row-major C (stride N)
// batched via blockIdx.z with element strides. Dims must be multiples of tile.
__global__ __launch_bounds__(256) void sgemm_nt(
    const float* __restrict__ A, const float* __restrict__ Bm,
    float* __restrict__ C, int M, int N, int K,
    long strideA, long strideB, long strideC)
{
    const int BM = 128, BN = 128, BK = 16;
    A  += (long)blockIdx.z * strideA;
    Bm += (long)blockIdx.z * strideB;
    C  += (long)blockIdx.z * strideC;
    __shared__ float As[BK][BM + 4];
    __shared__ float Bs[BK][BN + 4];
    int bm = blockIdx.y * BM, bn = blockIdx.x * BN;
    int t = threadIdx.x;
    int tm = (t / 16) * 8, tn = (t % 16) * 8;
    float acc[8][8] = {};
    const float* Aptr = A + (long)bm * K;
    const float* Bptr = Bm + (long)bn * K;
    for (int k0 = 0; k0 < K; k0 += BK) {
        #pragma unroll
        for (int i = 0; i < 2; i++) {
            int fid = t + i * 256;          // 512 float4s per tile
            int r = fid >> 2;
            int c4 = (fid & 3) * 4;
            float4 va = *(const float4*)&Aptr[(long)r * K + k0 + c4];
            As[c4 + 0][r] = va.x; As[c4 + 1][r] = va.y;
            As[c4 + 2][r] = va.z; As[c4 + 3][r] = va.w;
            float4 vb = *(const float4*)&Bptr[(long)r * K + k0 + c4];
            Bs[c4 + 0][r] = vb.x; Bs[c4 + 1][r] = vb.y;
            Bs[c4 + 2][r] = vb.z; Bs[c4 + 3][r] = vb.w;
        }
        __syncthreads();
        #pragma unroll
        for (int k = 0; k < BK; k++) {
            float a[8], b[8];
            #pragma unroll
            for (int i = 0; i < 8; i++) a[i] = As[k][tm + i];
            #pragma unroll
            for (int j = 0; j < 8; j++) b[j] = Bs[k][tn + j];
            #pragma unroll
            for (int i = 0; i < 8; i++)
                #pragma unroll
                for (int j = 0; j < 8; j++)
                    acc[i][j] = fmaf(a[i], b[j], acc[i][j]);
        }
        __syncthreads();
    }
    #pragma unroll
    for (int i = 0; i < 8; i++) {
        float4* cp = (float4*)&C[(long)(bm + tm + i) * N + bn + tn];
        cp[0] = make_float4(acc[i][0], acc[i][1], acc[i][2], acc[i][3]);
        cp[1] = make_float4(acc[i][4], acc[i][5], acc[i][6], acc[i][7]);
    }
}

// --------------------------------- launch --------------------------------------
extern "C" void kernel_launch(void* const* d_in, const int* in_sizes, int n_in,
                              void* d_out, int out_size) {
    const float* key_soft = (const float*)d_in[0];   // [16,1024,256]
    const float* keys     = (const float*)d_in[1];   // [512,256]
    const float* vparams  = (const float*)d_in[2];   // [512,256]
    float* out = (float*)d_out;

    // output layout = tuple order, all float32
    float* o_idx  = out;                             // [16384]
    float* o_vw   = o_idx  + MR;                     // [16384,256]
    float* o_hard = o_vw   + (long)MR * DD;          // [16384,256]
    float* o_vpss = o_hard + (long)MR * DD;          // [16,1024,1024]
    float* o_vpsh = o_vpss + (long)MR * TT;          // [16384,512]
    float* o_kss  = o_vpsh + (long)MR * NE;          // [16,1024,1024]
    float* o_ksh  = o_kss  + (long)MR * TT;          // [16384,512]

    float *p_ksn, *p_w, *p_kn, *p_vpn, *p_vpnT;
    cudaGetSymbolAddress((void**)&p_ksn,  g_ksn);
    cudaGetSymbolAddress((void**)&p_w,    g_w);
    cudaGetSymbolAddress((void**)&p_kn,   g_keys_norm);
    cudaGetSymbolAddress((void**)&p_vpn,  g_vp_norm);
    cudaGetSymbolAddress((void**)&p_vpnT, g_vp_normT);

    // 1) normalize codebooks + inputs
    rownorm256<<<NE, 256>>>(keys,     p_kn);
    rownorm256<<<NE, 256>>>(vparams,  p_vpn);
    transpose_vp<<<dim3(DD / 32, NE / 32), dim3(32, 32)>>>();
    rownorm256<<<MR, 256>>>(key_soft, p_ksn);

    // 2) score_ksh = ksn @ keys_norm^T   [16384,512]
    sgemm_nt<<<dim3(NE / 128, MR / 128, 1), 256>>>(
        p_ksn, p_kn, o_ksh, MR, NE, DD, 0, 0, 0);

    // 3) softmax/argmax/hard-gather (writes g_w, o_idx, o_hard)
    softmax_argmax<<<MR, 256>>>(o_ksh, o_idx, o_hard);

    // 4) vw_raw = w @ vp_norm  ==  w @ (vp_normT)^T   [16384,256]
    sgemm_nt<<<dim3(DD / 128, MR / 128, 1), 256>>>(
        p_w, p_vpnT, o_vw, MR, DD, NE, 0, 0, 0);

    // 5) normalize vparams_w in place
    rownorm256<<<MR, 256>>>(o_vw, o_vw);

    // 6) score_vpsh = vparams_w @ vp_norm^T   [16384,512]
    sgemm_nt<<<dim3(NE / 128, MR / 128, 1), 256>>>(
        o_vw, p_vpn, o_vpsh, MR, NE, DD, 0, 0, 0);

    // 7) score_kss  = batched ksn_b @ ksn_b^T   [16,1024,1024]
    sgemm_nt<<<dim3(TT / 128, TT / 128, BB), 256>>>(
        p_ksn, p_ksn, o_kss, TT, TT, DD,
        (long)TT * DD, (long)TT * DD, (long)TT * TT);

    // 8) score_vpss = batched vw_b @ vw_b^T     [16,1024,1024]
    sgemm_nt<<<dim3(TT / 128, TT / 128, BB), 256>>>(
        o_vw, o_vw, o_vpss, TT, TT, DD,
        (long)TT * DD, (long)TT * DD, (long)TT * TT);
}

// round 2
// speedup vs baseline: 1.0023x; 1.0023x over previous
#include <cuda_runtime.h>
#include <math.h>

// Problem dims (fixed by the dataset)
#define BB   16
#define TT   1024
#define DD   256        // key_dim == e_dim
#define NE   512        // codebook size
#define MR   (BB*TT)    // 16384 rows

// ---------------- scratch (__device__ globals: allocation-free) ----------------
__device__ float g_ksn[MR * DD];        // normalized key_soft         (16 MB)
__device__ float g_w[MR * NE];          // softmax weights             (32 MB)
__device__ float g_keys_norm[NE * DD];  // normalized keys
__device__ float g_vp_norm[NE * DD];    // normalized vparams
__device__ float g_vp_normT[DD * NE];   // vp_norm transposed [E, n_e]

// ---------------- rowwise L2 normalize, 256 cols, one block per row ------------
__global__ void rownorm256(const float* __restrict__ in, float* __restrict__ out) {
    int r = blockIdx.x;
    int t = threadIdx.x;                  // 256 threads
    float v = in[(long)r * 256 + t];
    float s = v * v;
    #pragma unroll
    for (int o = 16; o; o >>= 1) s += __shfl_xor_sync(0xffffffffu, s, o);
    __shared__ float ws[8];
    if ((t & 31) == 0) ws[t >> 5] = s;
    __syncthreads();
    if (t < 8) {
        float x = ws[t];
        #pragma unroll
        for (int o = 4; o; o >>= 1) x += __shfl_xor_sync(0xffu, x, o);
        if (t == 0) ws[0] = x;
    }
    __syncthreads();
    float scale = 1.0f / fmaxf(sqrtf(ws[0]), 1e-12f);
    out[(long)r * 256 + t] = v * scale;
}

// ---------------- transpose vp_norm [512,256] -> vp_normT [256,512] ------------
__global__ void transpose_vp() {
    __shared__ float tile[32][33];
    int x = blockIdx.x * 32 + threadIdx.x;   // src col (0..255)
    int y = blockIdx.y * 32 + threadIdx.y;   // src row (0..511)
    tile[threadIdx.y][threadIdx.x] = g_vp_norm[y * 256 + x];
    __syncthreads();
    int tx = blockIdx.y * 32 + threadIdx.x;  // dst col = src row
    int ty = blockIdx.x * 32 + threadIdx.y;  // dst row = src col
    g_vp_normT[ty * 512 + tx] = tile[threadIdx.x][threadIdx.y];
}

// ---------------- softmax + argmax + hard gather, one block per row ------------
// reads score_ksh row (512), writes g_w row, idx (as float), and vparams_hard row
__global__ void softmax_argmax(const float* __restrict__ ksh,
                               float* __restrict__ out_idx,
                               float* __restrict__ out_hard) {
    int r = blockIdx.x;
    int t = threadIdx.x;                  // 256 threads, 2 cols each
    const float* row = ksh + (long)r * NE;
    float s0 = row[t], s1 = row[t + 256];
    float bv; int bi;
    if (s1 > s0) { bv = s1; bi = t + 256; } else { bv = s0; bi = t; } // tie -> lower idx
    #pragma unroll
    for (int o = 16; o; o >>= 1) {
        float ov = __shfl_xor_sync(0xffffffffu, bv, o);
        int   oi = __shfl_xor_sync(0xffffffffu, bi, o);
        if (ov > bv || (ov == bv && oi < bi)) { bv = ov; bi = oi; }
    }
    __shared__ float sv[8]; __shared__ int si[8];
    if ((t & 31) == 0) { sv[t >> 5] = bv; si[t >> 5] = bi; }
    __syncthreads();
    if (t < 8) {
        float x = sv[t]; int xi = si[t];
        #pragma unroll
        for (int o = 4; o; o >>= 1) {
            float ov = __shfl_xor_sync(0xffu, x, o);
            int   oi = __shfl_xor_sync(0xffu, xi, o);
            if (ov > x || (ov == x && oi < xi)) { x = ov; xi = oi; }
        }
        if (t == 0) { sv[0] = x; si[0] = xi; }
    }
    __syncthreads();
    float m = sv[0]; int idx = si[0];
    float e0 = expf(s0 - m), e1 = expf(s1 - m);
    float s = e0 + e1;
    #pragma unroll
    for (int o = 16; o; o >>= 1) s += __shfl_xor_sync(0xffffffffu, s, o);
    __shared__ float ss[8];
    if ((t & 31) == 0) ss[t >> 5] = s;
    __syncthreads();
    if (t < 8) {
        float x = ss[t];
        #pragma unroll
        for (int o = 4; o; o >>= 1) x += __shfl_xor_sync(0xffu, x, o);
        if (t == 0) ss[0] = x;
    }
    __syncthreads();
    float inv = 1.0f / ss[0];
    g_w[(long)r * NE + t]       = e0 * inv;
    g_w[(long)r * NE + t + 256] = e1 * inv;
    if (t == 0) out_idx[r] = (float)idx;
    // vparams_hard = l2norm(vparams[idx]) == vp_norm[idx]
    out_hard[(long)r * 256 + t] = g_vp_norm[(long)idx * 256 + t];
}

// ---------------- generic NT SGEMM: C[M,N] = A[M,K] * B[N,K]^T -----------------
// row-major A (stride K), row-major B (stride K), row-major C (stride N)
// batched via blockIdx.z with element strides. Dims must be multiples of tile.
__global__ __launch_bounds__(256) void sgemm_nt(
    const float* __restrict__ A, const float* __restrict__ Bm,
    float* __restrict__ C, int M, int N, int K,
    long strideA, long strideB, long strideC)
{
    const int BM = 128, BN = 128, BK = 16;
    A  += (long)blockIdx.z * strideA;
    Bm += (long)blockIdx.z * strideB;
    C  += (long)blockIdx.z * strideC;
    __shared__ float As[BK][BM + 4];
    __shared__ float Bs[BK][BN + 4];
    int bm = blockIdx.y * BM, bn = blockIdx.x * BN;
    int t = threadIdx.x;
    int tm = (t / 16) * 8, tn = (t % 16) * 8;
    float acc[8][8] = {};
    const float* Aptr = A + (long)bm * K;
    const float* Bptr = Bm + (long)bn * K;
    for (int k0 = 0; k0 < K; k0 += BK) {
        #pragma unroll
        for (int i = 0; i < 2; i++) {
            int fid = t + i * 256;          // 512 float4s per tile
            int r = fid >> 2;
            int c4 = (fid & 3) * 4;
            float4 va = *(const float4*)&Aptr[(long)r * K + k0 + c4];
            As[c4 + 0][r] = va.x; As[c4 + 1][r] = va.y;
            As[c4 + 2][r] = va.z; As[c4 + 3][r] = va.w;
            float4 vb = *(const float4*)&Bptr[(long)r * K + k0 + c4];
            Bs[c4 + 0][r] = vb.x; Bs[c4 + 1][r] = vb.y;
            Bs[c4 + 2][r] = vb.z; Bs[c4 + 3][r] = vb.w;
        }
        __syncthreads();
        #pragma unroll
        for (int k = 0; k < BK; k++) {
            float a[8], b[8];
            #pragma unroll
            for (int i = 0; i < 8; i++) a[i] = As[k][tm + i];
            #pragma unroll
            for (int j = 0; j < 8; j++) b[j] = Bs[k][tn + j];
            #pragma unroll
            for (int i = 0; i < 8; i++)
                #pragma unroll
                for (int j = 0; j < 8; j++)
                    acc[i][j] = fmaf(a[i], b[j], acc[i][j]);
        }
        __syncthreads();
    }
    #pragma unroll
    for (int i = 0; i < 8; i++) {
        float4* cp = (float4*)&C[(long)(bm + tm + i) * N + bn + tn];
        cp[0] = make_float4(acc[i][0], acc[i][1], acc[i][2], acc[i][3]);
        cp[1] = make_float4(acc[i][4], acc[i][5], acc[i][6], acc[i][7]);
    }
}

// --------------------------------- launch --------------------------------------
extern "C" void kernel_launch(void* const* d_in, const int* in_sizes, int n_in,
                              void* d_out, int out_size) {
    const float* key_soft = (const float*)d_in[0];   // [16,1024,256]
    const float* keys     = (const float*)d_in[1];   // [512,256]
    const float* vparams  = (const float*)d_in[2];   // [512,256]
    float* out = (float*)d_out;

    // output layout = tuple order, all float32
    float* o_idx  = out;                             // [16384]
    float* o_vw   = o_idx  + MR;                     // [16384,256]
    float* o_hard = o_vw   + (long)MR * DD;          // [16384,256]
    float* o_vpss = o_hard + (long)MR * DD;          // [16,1024,1024]
    float* o_vpsh = o_vpss + (long)MR * TT;          // [16384,512]
    float* o_kss  = o_vpsh + (long)MR * NE;          // [16,1024,1024]
    float* o_ksh  = o_kss  + (long)MR * TT;          // [16384,512]

    float *p_ksn, *p_w, *p_kn, *p_vpn, *p_vpnT;
    cudaGetSymbolAddress((void**)&p_ksn,  g_ksn);
    cudaGetSymbolAddress((void**)&p_w,    g_w);
    cudaGetSymbolAddress((void**)&p_kn,   g_keys_norm);
    cudaGetSymbolAddress((void**)&p_vpn,  g_vp_norm);
    cudaGetSymbolAddress((void**)&p_vpnT, g_vp_normT);

    // 1) normalize codebooks + inputs
    rownorm256<<<NE, 256>>>(keys,     p_kn);
    rownorm256<<<NE, 256>>>(vparams,  p_vpn);
    transpose_vp<<<dim3(DD / 32, NE / 32), dim3(32, 32)>>>();
    rownorm256<<<MR, 256>>>(key_soft, p_ksn);

    // 2) score_ksh = ksn @ keys_norm^T   [16384,512]
    sgemm_nt<<<dim3(NE / 128, MR / 128, 1), 256>>>(
        p_ksn, p_kn, o_ksh, MR, NE, DD, 0, 0, 0);

    // 3) softmax/argmax/hard-gather (writes g_w, o_idx, o_hard)
    softmax_argmax<<<MR, 256>>>(o_ksh, o_idx, o_hard);

    // 4) vw_raw = w @ vp_norm  ==  w @ (vp_normT)^T   [16384,256]
    sgemm_nt<<<dim3(DD / 128, MR / 128, 1), 256>>>(
        p_w, p_vpnT, o_vw, MR, DD, NE, 0, 0, 0);

    // 5) normalize vparams_w in place
    rownorm256<<<MR, 256>>>(o_vw, o_vw);

    // 6) score_vpsh = vparams_w @ vp_norm^T   [16384,512]
    sgemm_nt<<<dim3(NE / 128, MR / 128, 1), 256>>>(
        o_vw, p_vpn, o_vpsh, MR, NE, DD, 0, 0, 0);

    // 7) score_kss  = batched ksn_b @ ksn_b^T   [16,1024,1024]
    sgemm_nt<<<dim3(TT / 128, TT / 128, BB), 256>>>(
        p_ksn, p_ksn, o_kss, TT, TT, DD,
        (long)TT * DD, (long)TT * DD, (long)TT * TT);

    // 8) score_vpss = batched vw_b @ vw_b^T     [16,1024,1024]
    sgemm_nt<<<dim3(TT / 128, TT / 128, BB), 256>>>(
        o_vw, o_vw, o_vpss, TT, TT, DD,
        (long)TT * DD, (long)TT * DD, (long)TT * TT);
}